// round 15
// baseline (speedup 1.0000x reference)
#include <cuda_runtime.h>
#include <math.h>

#define MAXN 400000
#define MAXE 6400000
#define MAXG 1024
#define EMB  12

// ---------------- static scratch ----------------
__device__ int   g_deg [MAXN];
__device__ float g_dinv[MAXN];
__device__ float g_s   [MAXN];                 // row-sum of A_norm (written by L0 gather)
__device__ int   g_off [MAXN];
__device__ int   g_cur [MAXN];
__device__ unsigned long long g_tilestat[512];
__device__ int2  g_epack[MAXE];                // (src row, __float_as_int(norm))
__device__ float g_hA [3][(size_t)MAXN*4];     // h chunks, ping
__device__ float g_hB [3][(size_t)MAXN*4];     // h chunks, pong
__device__ float g_agg[3][(size_t)MAXN*4];     // gather outputs (A_norm * h)
__device__ float g_gsum[MAXG*EMB];
__device__ float g_gmax[MAXG*EMB];
__device__ float g_cnt [MAXG];

__device__ __forceinline__ void atomicMaxF(float* addr, float v) {
    int vi = __float_as_int(v);
    if (vi >= 0) atomicMax((int*)addr, vi);
    else         atomicMin((unsigned int*)addr, __float_as_uint(v));
}

// ---------------- structure passes (validated verbatim) ----------------
__global__ void k_deg(const int* __restrict__ colp, int E) {
    int base = (blockIdx.x * blockDim.x + threadIdx.x) * 4;
    if (base >= E) return;
    int n = min(4, E - base);
    int c[4];
    #pragma unroll
    for (int k = 0; k < 4; k++) if (k < n) c[k] = __ldg(&colp[base + k]);
    #pragma unroll
    for (int k = 0; k < 4; k++) if (k < n) atomicAdd(&g_deg[c[k]], 1);
}

__global__ void k_scan(int N) {
    __shared__ int sh[1024];
    __shared__ int s_prefix;
    int t = threadIdx.x;
    int b = blockIdx.x;
    int i = b * 1024 + t;

    int deg = (i < N) ? g_deg[i] : 0;
    if (i < N) g_dinv[i] = rsqrtf((float)(deg + 1));
    int v = (i < N) ? deg : 0;

    sh[t] = v; __syncthreads();
    for (int o = 1; o < 1024; o <<= 1) {
        int x2 = (t >= o) ? sh[t - o] : 0; __syncthreads();
        sh[t] += x2; __syncthreads();
    }
    int incl  = sh[t];
    int total = sh[1023];

    if (t == 0) {
        volatile unsigned long long* ts = (volatile unsigned long long*)g_tilestat;
        int pfx = 0;
        if (b > 0) {
            ts[b] = (1ULL << 62) | (unsigned)total;
            int p = b - 1;
            for (;;) {
                unsigned long long st = ts[p];
                unsigned s2 = (unsigned)(st >> 62);
                if (s2 == 0u) continue;
                pfx += (int)(unsigned)(st & 0xffffffffULL);
                if (s2 == 2u) break;
                --p;
            }
        }
        ts[b] = (2ULL << 62) | (unsigned)(pfx + total);
        s_prefix = pfx;
    }
    __syncthreads();
    if (i < N) {
        int off = s_prefix + incl - v;
        g_off[i] = off;
        g_cur[i] = off;
    }
}

__global__ void k_build(const int* __restrict__ rowp,
                        const int* __restrict__ colp, int E) {
    int base = (blockIdx.x * blockDim.x + threadIdx.x) * 4;
    if (base >= E) return;
    int n = min(4, E - base);

    int r[4], c[4], pos[4];
    float dr[4], dc[4];
    #pragma unroll
    for (int k = 0; k < 4; k++) if (k < n) { r[k] = __ldg(&rowp[base+k]); c[k] = __ldg(&colp[base+k]); }
    #pragma unroll
    for (int k = 0; k < 4; k++) if (k < n) pos[k] = atomicAdd(&g_cur[c[k]], 1);
    #pragma unroll
    for (int k = 0; k < 4; k++) if (k < n) { dr[k] = g_dinv[r[k]]; dc[k] = g_dinv[c[k]]; }
    #pragma unroll
    for (int k = 0; k < 4; k++) if (k < n)
        g_epack[pos[k]] = make_int2(r[k], __float_as_int(dr[k] * dc[k]));
}

// ---------------- gather pass: agg_c = A_norm * h_c (4 features) ----------
// Verbatim body of the measured-fast FIN4 layer, minus the GEMV epilogue.
// hin: [N][4] (16B rows). aggout: [N][4]. write_s: L0 only, stores row-sum.
__global__ void __launch_bounds__(256) k_gather(
        const float* __restrict__ hin, float* __restrict__ aggout,
        int N, int write_s) {
    int hw     = threadIdx.x >> 4;
    int lane16 = threadIdx.x & 15;
    unsigned hmask = 0xFFFFu << (((threadIdx.x & 31) >> 4) << 4);

    int i = blockIdx.x * 16 + hw;
    if (i >= N) return;

    float di = g_dinv[i];
    float sn = di * di;
    float acc = (lane16 < 4) ? sn * __ldg(&hin[(size_t)i * 4 + lane16]) : 0.f;
    float s   = sn;

    int beg = g_off[i];
    int cnt = g_deg[i];
    const int2* ep = g_epack + beg;

    int j0 = 0;
    for (; j0 + 16 <= cnt; j0 += 16) {
        int2 e = __ldg(&ep[j0 + lane16]);
        #pragma unroll
        for (int q = 0; q < 16; q++) {
            int   r  = __shfl_sync(hmask, e.x, q, 16);
            float nm = __int_as_float(__shfl_sync(hmask, e.y, q, 16));
            s += nm;
            float hv = (lane16 < 4) ? __ldg(&hin[(size_t)r * 4 + lane16]) : 0.f;
            acc = fmaf(nm, hv, acc);
        }
    }
    int rem = cnt - j0;
    if (rem > 0) {
        int2 e = (lane16 < rem) ? __ldg(&ep[j0 + lane16]) : make_int2(0, 0);
        for (int q = 0; q < rem; q++) {
            int   r  = __shfl_sync(hmask, e.x, q, 16);
            float nm = __int_as_float(__shfl_sync(hmask, e.y, q, 16));
            s += nm;
            float hv = (lane16 < 4) ? __ldg(&hin[(size_t)r * 4 + lane16]) : 0.f;
            acc = fmaf(nm, hv, acc);
        }
    }

    if (lane16 < 4) aggout[(size_t)i * 4 + lane16] = acc;
    if (write_s && lane16 == 4) g_s[i] = s;
}

// ---------------- dense stage: out_c = tanh(agg @ W + s*b), chunked -------
template<int FIN>
__global__ void __launch_bounds__(256) k_dense(
        const float* __restrict__ a0, const float* __restrict__ a1,
        const float* __restrict__ a2,
        float* __restrict__ o0, float* __restrict__ o1, float* __restrict__ o2,
        const float* __restrict__ W, const float* __restrict__ b, int N) {
    __shared__ float sW[FIN * EMB];
    __shared__ float sB[EMB];
    for (int t = threadIdx.x; t < FIN * EMB; t += blockDim.x) sW[t] = W[t];
    if (threadIdx.x < EMB) sB[threadIdx.x] = b[threadIdx.x];
    __syncthreads();

    int i = blockIdx.x * blockDim.x + threadIdx.x;
    if (i >= N) return;

    float in[FIN];
    {
        float4 v = __ldg(&((const float4*)a0)[i]);
        in[0] = v.x; in[1] = v.y; in[2] = v.z; in[3] = v.w;
    }
    if (FIN == 12) {
        float4 v1 = __ldg(&((const float4*)a1)[i]);
        float4 v2 = __ldg(&((const float4*)a2)[i]);
        in[4] = v1.x; in[5] = v1.y; in[6]  = v1.z; in[7]  = v1.w;
        in[8] = v2.x; in[9] = v2.y; in[10] = v2.z; in[11] = v2.w;
    }

    float s = __ldg(&g_s[i]);
    float o[EMB];
    #pragma unroll
    for (int k = 0; k < EMB; k++) {
        float a = s * sB[k];
        #pragma unroll
        for (int f = 0; f < FIN; f++) a = fmaf(in[f], sW[f * EMB + k], a);
        o[k] = tanhf(a);
    }

    ((float4*)o0)[i] = make_float4(o[0], o[1], o[2],  o[3]);
    ((float4*)o1)[i] = make_float4(o[4], o[5], o[6],  o[7]);
    ((float4*)o2)[i] = make_float4(o[8], o[9], o[10], o[11]);
}

// ---------------- pooling (validated; reads 3 chunk arrays) ----------------
__global__ void k_pool(const float* __restrict__ c0, const float* __restrict__ c1,
                       const float* __restrict__ c2,
                       const int* __restrict__ batch, int N) {
    int i = blockIdx.x * blockDim.x + threadIdx.x;
    bool act = i < N;
    int g = act ? batch[i] : -1;
    float v[EMB];
    if (act) {
        float4 a  = __ldg(&((const float4*)c0)[i]);
        float4 bq = __ldg(&((const float4*)c1)[i]);
        float4 c  = __ldg(&((const float4*)c2)[i]);
        v[0]=a.x; v[1]=a.y; v[2]=a.z; v[3]=a.w;
        v[4]=bq.x; v[5]=bq.y; v[6]=bq.z; v[7]=bq.w;
        v[8]=c.x; v[9]=c.y; v[10]=c.z; v[11]=c.w;
    } else {
        #pragma unroll
        for (int f = 0; f < EMB; f++) v[f] = 0.f;
    }
    unsigned full = 0xFFFFFFFFu;
    int g0 = __shfl_sync(full, g, 0);
    bool uni = __all_sync(full, g == g0);
    int lane = threadIdx.x & 31;

    if (uni && g0 >= 0) {
        float sm[EMB], mx[EMB];
        #pragma unroll
        for (int f = 0; f < EMB; f++) { sm[f] = v[f]; mx[f] = v[f]; }
        #pragma unroll
        for (int o = 16; o > 0; o >>= 1) {
            #pragma unroll
            for (int f = 0; f < EMB; f++) {
                sm[f] += __shfl_down_sync(full, sm[f], o);
                mx[f] = fmaxf(mx[f], __shfl_down_sync(full, mx[f], o));
            }
        }
        if (lane == 0) {
            #pragma unroll
            for (int f = 0; f < EMB; f++) {
                atomicAdd(&g_gsum[g0 * EMB + f], sm[f]);
                atomicMaxF(&g_gmax[g0 * EMB + f], mx[f]);
            }
            atomicAdd(&g_cnt[g0], 32.f);
        }
    } else if (act) {
        #pragma unroll
        for (int f = 0; f < EMB; f++) {
            atomicAdd(&g_gsum[g * EMB + f], v[f]);
            atomicMaxF(&g_gmax[g * EMB + f], v[f]);
        }
        atomicAdd(&g_cnt[g], 1.f);
    }
}

// ---------------- head (validated) ----------------
__global__ void k_final(const float* __restrict__ Wout, const float* __restrict__ bout,
                        float* __restrict__ out, int G) {
    int g = blockIdx.x;
    int t = threadIdx.x;
    __shared__ float hid[2 * EMB];
    if (t < 2 * EMB) {
        float v;
        if (t < EMB) v = g_gmax[g * EMB + t];
        else         v = g_gsum[g * EMB + (t - EMB)] / fmaxf(g_cnt[g], 1.f);
        hid[t] = v;
        out[(size_t)G * 17 + (size_t)g * 24 + t] = v;
    }
    __syncthreads();
    if (t < 17) {
        float o = bout[t];
        #pragma unroll
        for (int f = 0; f < 2 * EMB; f++) o += hid[f] * Wout[f * 17 + t];
        out[(size_t)g * 17 + t] = o;
    }
}

// ---------------- launch ----------------
extern "C" void kernel_launch(void* const* d_in, const int* in_sizes, int n_in,
                              void* d_out, int out_size) {
    const float* x     = (const float*)d_in[0];
    const int*   eidx  = (const int*)  d_in[1];
    const int*   batch = (const int*)  d_in[2];
    const float* W0 = (const float*)d_in[3],  *b0 = (const float*)d_in[4];
    const float* W1 = (const float*)d_in[5],  *b1 = (const float*)d_in[6];
    const float* W2 = (const float*)d_in[7],  *b2 = (const float*)d_in[8];
    const float* W3 = (const float*)d_in[9],  *b3 = (const float*)d_in[10];
    const float* Wo = (const float*)d_in[11], *bo = (const float*)d_in[12];
    float* out = (float*)d_out;

    const int N = in_sizes[0] / 4;
    const int E = in_sizes[1] / 2;
    const int G = out_size / 41;           // 17 + 24 per graph

    const int* rowp = eidx;
    const int* colp = eidx + E;

    // init via memset nodes (validated)
    void *pDeg, *pGsum, *pGmax, *pCnt, *pTs;
    cudaGetSymbolAddress(&pDeg,  g_deg);
    cudaGetSymbolAddress(&pGsum, g_gsum);
    cudaGetSymbolAddress(&pGmax, g_gmax);
    cudaGetSymbolAddress(&pCnt,  g_cnt);
    cudaGetSymbolAddress(&pTs,   g_tilestat);
    cudaMemsetAsync(pDeg,  0,    (size_t)N * sizeof(int), 0);
    cudaMemsetAsync(pGsum, 0,    (size_t)G * EMB * sizeof(float), 0);
    cudaMemsetAsync(pGmax, 0xFF, (size_t)G * EMB * sizeof(float), 0);   // -NaN ≡ -inf for atomicMaxF
    cudaMemsetAsync(pCnt,  0,    (size_t)G * sizeof(float), 0);
    cudaMemsetAsync(pTs,   0,    512 * sizeof(unsigned long long), 0);

    const int T = 256;
    int nbN   = (N + T - 1) / T;
    int nbE4  = (E + T * 4 - 1) / (T * 4);
    int nScan = (N + 1023) / 1024;
    int nbL   = (N + 15) / 16;

    k_deg<<<nbE4, T>>>(colp, E);                          // 0
    k_scan<<<nScan, 1024>>>(N);                           // 1
    k_build<<<nbE4, T>>>(rowp, colp, E);                  // 2

    // ---- Layer 0: x (already [N][4]) -> gather -> dense(4->12) into A ----
    k_gather<<<nbL, T>>>(x, g_agg[0], N, 1);              // 3 <- PROFILED (reads x, fast config)
    k_dense<4><<<nbN, T>>>(g_agg[0], 0, 0,
                           g_hA[0], g_hA[1], g_hA[2], W0, b0, N);         // 4

    // ---- Layer 1: A -> agg -> dense -> B ----
    k_gather<<<nbL, T>>>(g_hA[0], g_agg[0], N, 0);        // 5
    k_gather<<<nbL, T>>>(g_hA[1], g_agg[1], N, 0);        // 6
    k_gather<<<nbL, T>>>(g_hA[2], g_agg[2], N, 0);        // 7
    k_dense<12><<<nbN, T>>>(g_agg[0], g_agg[1], g_agg[2],
                            g_hB[0], g_hB[1], g_hB[2], W1, b1, N);        // 8

    // ---- Layer 2: B -> agg -> dense -> A ----
    k_gather<<<nbL, T>>>(g_hB[0], g_agg[0], N, 0);        // 9
    k_gather<<<nbL, T>>>(g_hB[1], g_agg[1], N, 0);        // 10
    k_gather<<<nbL, T>>>(g_hB[2], g_agg[2], N, 0);        // 11
    k_dense<12><<<nbN, T>>>(g_agg[0], g_agg[1], g_agg[2],
                            g_hA[0], g_hA[1], g_hA[2], W2, b2, N);        // 12

    // ---- Layer 3: A -> agg -> dense -> B ----
    k_gather<<<nbL, T>>>(g_hA[0], g_agg[0], N, 0);        // 13
    k_gather<<<nbL, T>>>(g_hA[1], g_agg[1], N, 0);        // 14
    k_gather<<<nbL, T>>>(g_hA[2], g_agg[2], N, 0);        // 15
    k_dense<12><<<nbN, T>>>(g_agg[0], g_agg[1], g_agg[2],
                            g_hB[0], g_hB[1], g_hB[2], W3, b3, N);        // 16

    k_pool<<<nbN, T>>>(g_hB[0], g_hB[1], g_hB[2], batch, N);              // 17
    k_final<<<G, 32>>>(Wo, bo, out, G);                                   // 18
}

// round 16
// speedup vs baseline: 16.5115x; 16.5115x over previous
#include <cuda_runtime.h>
#include <math.h>

#define MAXN 400000
#define MAXE 6400000
#define MAXG 1024
#define EMB  12

// ---------------- static scratch ----------------
__device__ int   g_deg [MAXN];
__device__ float g_dinv[MAXN];
__device__ int   g_off [MAXN];
__device__ int   g_cur [MAXN];
__device__ unsigned long long g_tilestat[512];
__device__ int   g_stash[(size_t)2*MAXE];   // preserved copy of edge_index (streamed only)
__device__ int2  g_epack[MAXE];             // (src row, norm) — streamed only
__device__ float g_ha  [(size_t)MAXN*16];   // fallback ping (if input buffer too small)
__device__ float g_hb  [(size_t)MAXN*16];   // fallback pong
__device__ float g_gsum[MAXG*EMB];
__device__ float g_gmax[MAXG*EMB];
__device__ float g_cnt [MAXG];

__device__ __forceinline__ void atomicMaxF(float* addr, float v) {
    int vi = __float_as_int(v);
    if (vi >= 0) atomicMax((int*)addr, vi);
    else         atomicMin((unsigned int*)addr, __float_as_uint(v));
}

// ---------------- structure passes (validated verbatim) ----------------
__global__ void k_deg(const int* __restrict__ colp, int E) {
    int base = (blockIdx.x * blockDim.x + threadIdx.x) * 4;
    if (base >= E) return;
    int n = min(4, E - base);
    int c[4];
    #pragma unroll
    for (int k = 0; k < 4; k++) if (k < n) c[k] = __ldg(&colp[base + k]);
    #pragma unroll
    for (int k = 0; k < 4; k++) if (k < n) atomicAdd(&g_deg[c[k]], 1);
}

__global__ void k_scan(int N) {
    __shared__ int sh[1024];
    __shared__ int s_prefix;
    int t = threadIdx.x;
    int b = blockIdx.x;
    int i = b * 1024 + t;

    int deg = (i < N) ? g_deg[i] : 0;
    if (i < N) g_dinv[i] = rsqrtf((float)(deg + 1));
    int v = (i < N) ? deg : 0;

    sh[t] = v; __syncthreads();
    for (int o = 1; o < 1024; o <<= 1) {
        int x2 = (t >= o) ? sh[t - o] : 0; __syncthreads();
        sh[t] += x2; __syncthreads();
    }
    int incl  = sh[t];
    int total = sh[1023];

    if (t == 0) {
        volatile unsigned long long* ts = (volatile unsigned long long*)g_tilestat;
        int pfx = 0;
        if (b > 0) {
            ts[b] = (1ULL << 62) | (unsigned)total;
            int p = b - 1;
            for (;;) {
                unsigned long long st = ts[p];
                unsigned s2 = (unsigned)(st >> 62);
                if (s2 == 0u) continue;
                pfx += (int)(unsigned)(st & 0xffffffffULL);
                if (s2 == 2u) break;
                --p;
            }
        }
        ts[b] = (2ULL << 62) | (unsigned)(pfx + total);
        s_prefix = pfx;
    }
    __syncthreads();
    if (i < N) {
        int off = s_prefix + incl - v;
        g_off[i] = off;
        g_cur[i] = off;
    }
}

__global__ void k_build(const int* __restrict__ rowp,
                        const int* __restrict__ colp, int E) {
    int base = (blockIdx.x * blockDim.x + threadIdx.x) * 4;
    if (base >= E) return;
    int n = min(4, E - base);

    int r[4], c[4], pos[4];
    float dr[4], dc[4];
    #pragma unroll
    for (int k = 0; k < 4; k++) if (k < n) { r[k] = __ldg(&rowp[base+k]); c[k] = __ldg(&colp[base+k]); }
    #pragma unroll
    for (int k = 0; k < 4; k++) if (k < n) pos[k] = atomicAdd(&g_cur[c[k]], 1);
    #pragma unroll
    for (int k = 0; k < 4; k++) if (k < n) { dr[k] = g_dinv[r[k]]; dc[k] = g_dinv[c[k]]; }
    #pragma unroll
    for (int k = 0; k < 4; k++) if (k < n)
        g_epack[pos[k]] = make_int2(r[k], __float_as_int(dr[k] * dc[k]));
}

// ---------------- GCN layer (R7/R8-validated shfl body, verbatim) ----------
template<int FIN, int INSTRIDE>
__global__ void __launch_bounds__(256) k_layer(
        const float* __restrict__ hin, float* __restrict__ hout,
        const float* __restrict__ W, const float* __restrict__ b, int N) {
    __shared__ float sW[FIN * EMB];
    __shared__ float sB[EMB];
    for (int t = threadIdx.x; t < FIN * EMB; t += blockDim.x) sW[t] = W[t];
    if (threadIdx.x < EMB) sB[threadIdx.x] = b[threadIdx.x];
    __syncthreads();

    int hw     = threadIdx.x >> 4;
    int lane16 = threadIdx.x & 15;
    unsigned hmask = 0xFFFFu << (((threadIdx.x & 31) >> 4) << 4);

    int i = blockIdx.x * 16 + hw;
    if (i >= N) return;

    float di = g_dinv[i];
    float sn = di * di;
    float acc = (lane16 < FIN) ? sn * __ldg(&hin[(size_t)i * INSTRIDE + lane16]) : 0.f;
    float s   = sn;

    int beg = g_off[i];
    int cnt = g_deg[i];
    const int2* ep = g_epack + beg;

    int j0 = 0;
    for (; j0 + 16 <= cnt; j0 += 16) {
        int2 e = __ldg(&ep[j0 + lane16]);
        #pragma unroll
        for (int q = 0; q < 16; q++) {
            int   r  = __shfl_sync(hmask, e.x, q, 16);
            float nm = __int_as_float(__shfl_sync(hmask, e.y, q, 16));
            s += nm;
            float hv = (lane16 < FIN) ? __ldg(&hin[(size_t)r * INSTRIDE + lane16]) : 0.f;
            acc = fmaf(nm, hv, acc);
        }
    }
    int rem = cnt - j0;
    if (rem > 0) {
        int2 e = (lane16 < rem) ? __ldg(&ep[j0 + lane16]) : make_int2(0, 0);
        for (int q = 0; q < rem; q++) {
            int   r  = __shfl_sync(hmask, e.x, q, 16);
            float nm = __int_as_float(__shfl_sync(hmask, e.y, q, 16));
            s += nm;
            float hv = (lane16 < FIN) ? __ldg(&hin[(size_t)r * INSTRIDE + lane16]) : 0.f;
            acc = fmaf(nm, hv, acc);
        }
    }

    int k = (lane16 < EMB) ? lane16 : 0;
    float o = s * sB[k];
    #pragma unroll
    for (int f = 0; f < FIN; f++) {
        float af = __shfl_sync(hmask, acc, f, 16);
        o = fmaf(af, sW[f * EMB + k], o);
    }
    float res = (lane16 < EMB) ? tanhf(o) : 0.f;
    hout[(size_t)i * 16 + lane16] = res;
}

// ---------------- pooling (validated) ----------------
__global__ void k_pool(const float* __restrict__ h,
                       const int* __restrict__ batch, int N) {
    int i = blockIdx.x * blockDim.x + threadIdx.x;
    bool act = i < N;
    int g = act ? batch[i] : -1;
    float v[EMB];
    if (act) {
        const float4* hp = (const float4*)(h + (size_t)i * 16);
        float4 a = hp[0], bq = hp[1], c = hp[2];
        v[0]=a.x; v[1]=a.y; v[2]=a.z; v[3]=a.w;
        v[4]=bq.x; v[5]=bq.y; v[6]=bq.z; v[7]=bq.w;
        v[8]=c.x; v[9]=c.y; v[10]=c.z; v[11]=c.w;
    } else {
        #pragma unroll
        for (int f = 0; f < EMB; f++) v[f] = 0.f;
    }
    unsigned full = 0xFFFFFFFFu;
    int g0 = __shfl_sync(full, g, 0);
    bool uni = __all_sync(full, g == g0);
    int lane = threadIdx.x & 31;

    if (uni && g0 >= 0) {
        float sm[EMB], mx[EMB];
        #pragma unroll
        for (int f = 0; f < EMB; f++) { sm[f] = v[f]; mx[f] = v[f]; }
        #pragma unroll
        for (int o = 16; o > 0; o >>= 1) {
            #pragma unroll
            for (int f = 0; f < EMB; f++) {
                sm[f] += __shfl_down_sync(full, sm[f], o);
                mx[f] = fmaxf(mx[f], __shfl_down_sync(full, mx[f], o));
            }
        }
        if (lane == 0) {
            #pragma unroll
            for (int f = 0; f < EMB; f++) {
                atomicAdd(&g_gsum[g0 * EMB + f], sm[f]);
                atomicMaxF(&g_gmax[g0 * EMB + f], mx[f]);
            }
            atomicAdd(&g_cnt[g0], 32.f);
        }
    } else if (act) {
        #pragma unroll
        for (int f = 0; f < EMB; f++) {
            atomicAdd(&g_gsum[g * EMB + f], v[f]);
            atomicMaxF(&g_gmax[g * EMB + f], v[f]);
        }
        atomicAdd(&g_cnt[g], 1.f);
    }
}

// ---------------- head (validated) ----------------
__global__ void k_final(const float* __restrict__ Wout, const float* __restrict__ bout,
                        float* __restrict__ out, int G) {
    int g = blockIdx.x;
    int t = threadIdx.x;
    __shared__ float hid[2 * EMB];
    if (t < 2 * EMB) {
        float v;
        if (t < EMB) v = g_gmax[g * EMB + t];
        else         v = g_gsum[g * EMB + (t - EMB)] / fmaxf(g_cnt[g], 1.f);
        hid[t] = v;
        out[(size_t)G * 17 + (size_t)g * 24 + t] = v;
    }
    __syncthreads();
    if (t < 17) {
        float o = bout[t];
        #pragma unroll
        for (int f = 0; f < 2 * EMB; f++) o += hid[f] * Wout[f * 17 + t];
        out[(size_t)g * 17 + t] = o;
    }
}

// ---------------- launch ----------------
extern "C" void kernel_launch(void* const* d_in, const int* in_sizes, int n_in,
                              void* d_out, int out_size) {
    const float* x     = (const float*)d_in[0];
    int*         ebuf  = (int*)        d_in[1];   // edge_index buffer (repurposed, restored)
    const int*   batch = (const int*)  d_in[2];
    const float* W0 = (const float*)d_in[3],  *b0 = (const float*)d_in[4];
    const float* W1 = (const float*)d_in[5],  *b1 = (const float*)d_in[6];
    const float* W2 = (const float*)d_in[7],  *b2 = (const float*)d_in[8];
    const float* W3 = (const float*)d_in[9],  *b3 = (const float*)d_in[10];
    const float* Wo = (const float*)d_in[11], *bo = (const float*)d_in[12];
    float* out = (float*)d_out;

    const int N = in_sizes[0] / 4;
    const int E = in_sizes[1] / 2;
    const int G = out_size / 41;           // 17 + 24 per graph

    // ---- scratch symbol addresses ----
    void *pDeg, *pGsum, *pGmax, *pCnt, *pTs, *pStash, *pHa, *pHb;
    cudaGetSymbolAddress(&pDeg,   g_deg);
    cudaGetSymbolAddress(&pGsum,  g_gsum);
    cudaGetSymbolAddress(&pGmax,  g_gmax);
    cudaGetSymbolAddress(&pCnt,   g_cnt);
    cudaGetSymbolAddress(&pTs,    g_tilestat);
    cudaGetSymbolAddress(&pStash, g_stash);
    cudaGetSymbolAddress(&pHa,    g_ha);
    cudaGetSymbolAddress(&pHb,    g_hb);

    // ---- init via memset nodes (validated) ----
    cudaMemsetAsync(pDeg,  0,    (size_t)N * sizeof(int), 0);
    cudaMemsetAsync(pGsum, 0,    (size_t)G * EMB * sizeof(float), 0);
    cudaMemsetAsync(pGmax, 0xFF, (size_t)G * EMB * sizeof(float), 0);   // -NaN ≡ -inf for atomicMaxF
    cudaMemsetAsync(pCnt,  0,    (size_t)G * sizeof(float), 0);
    cudaMemsetAsync(pTs,   0,    512 * sizeof(unsigned long long), 0);

    // ---- stash edge_index (its buffer becomes h ping/pong scratch) ----
    cudaMemcpyAsync(pStash, ebuf, (size_t)2 * E * sizeof(int),
                    cudaMemcpyDeviceToDevice, 0);
    const int* srow = (const int*)pStash;
    const int* scol = srow + E;

    // h ping/pong inside the cudaMalloc'd edge buffer (2MB pages -> fast gather)
    float* hA;
    float* hB;
    if ((size_t)2 * E * sizeof(int) >= (size_t)2 * N * 16 * sizeof(float)) {
        hA = (float*)ebuf;
        hB = hA + (size_t)N * 16;
    } else {                                  // fallback: device globals
        hA = (float*)pHa;
        hB = (float*)pHb;
    }

    const int T = 256;
    int nbN   = (N + T - 1) / T;
    int nbE4  = (E + T * 4 - 1) / (T * 4);
    int nScan = (N + 1023) / 1024;
    int nbL   = (N + 15) / 16;

    k_deg<<<nbE4, T>>>(scol, E);                          // 0 (reads stash)
    k_scan<<<nScan, 1024>>>(N);                           // 1
    k_build<<<nbE4, T>>>(srow, scol, E);                  // 2 (reads stash)

    // validated dataflow: x -> hA -> hB -> hA -> hB; pool(hB)
    k_layer<4, 4>  <<<nbL, T>>>(x,  hA, W0, b0, N);       // 3 <- PROFILED
    k_layer<12,16> <<<nbL, T>>>(hA, hB, W1, b1, N);       // 4
    k_layer<12,16> <<<nbL, T>>>(hB, hA, W2, b2, N);       // 5
    k_layer<12,16> <<<nbL, T>>>(hA, hB, W3, b3, N);       // 6

    k_pool<<<nbN, T>>>(hB, batch, N);                     // 7
    k_final<<<G, 32>>>(Wo, bo, out, G);                   // 8

    // ---- restore edge_index buffer (determinism across replays) ----
    cudaMemcpyAsync(ebuf, pStash, (size_t)2 * E * sizeof(int),
                    cudaMemcpyDeviceToDevice, 0);
}

// round 17
// speedup vs baseline: 18.7385x; 1.1349x over previous
#include <cuda_runtime.h>
#include <math.h>

#define MAXN 400000
#define MAXE 6400000
#define MAXG 1024
#define EMB  12

// ---------------- static scratch ----------------
__device__ int   g_deg [MAXN];
__device__ float g_dinv[MAXN];
__device__ float g_s   [MAXN];              // Σ norms incl self (written by L0)
__device__ int   g_off [MAXN];
__device__ int   g_cur [MAXN];
__device__ unsigned long long g_tilestat[512];
__device__ int   g_stash[(size_t)2*MAXE];   // preserved copy of edge_index (streamed only)
__device__ int2  g_epack[MAXE];             // (src row, norm) — streamed only
__device__ float g_ha  [(size_t)MAXN*16];   // fallback ping
__device__ float g_hb  [(size_t)MAXN*16];   // fallback pong
__device__ float g_gsum[MAXG*EMB];
__device__ float g_gmax[MAXG*EMB];
__device__ float g_cnt [MAXG];

__device__ __forceinline__ void atomicMaxF(float* addr, float v) {
    int vi = __float_as_int(v);
    if (vi >= 0) atomicMax((int*)addr, vi);
    else         atomicMin((unsigned int*)addr, __float_as_uint(v));
}

// ---------------- structure passes (validated verbatim) ----------------
__global__ void k_deg(const int* __restrict__ colp, int E) {
    int base = (blockIdx.x * blockDim.x + threadIdx.x) * 4;
    if (base >= E) return;
    int n = min(4, E - base);
    int c[4];
    #pragma unroll
    for (int k = 0; k < 4; k++) if (k < n) c[k] = __ldg(&colp[base + k]);
    #pragma unroll
    for (int k = 0; k < 4; k++) if (k < n) atomicAdd(&g_deg[c[k]], 1);
}

__global__ void k_scan(int N) {
    __shared__ int sh[1024];
    __shared__ int s_prefix;
    int t = threadIdx.x;
    int b = blockIdx.x;
    int i = b * 1024 + t;

    int deg = (i < N) ? g_deg[i] : 0;
    if (i < N) g_dinv[i] = rsqrtf((float)(deg + 1));
    int v = (i < N) ? deg : 0;

    sh[t] = v; __syncthreads();
    for (int o = 1; o < 1024; o <<= 1) {
        int x2 = (t >= o) ? sh[t - o] : 0; __syncthreads();
        sh[t] += x2; __syncthreads();
    }
    int incl  = sh[t];
    int total = sh[1023];

    if (t == 0) {
        volatile unsigned long long* ts = (volatile unsigned long long*)g_tilestat;
        int pfx = 0;
        if (b > 0) {
            ts[b] = (1ULL << 62) | (unsigned)total;
            int p = b - 1;
            for (;;) {
                unsigned long long st = ts[p];
                unsigned s2 = (unsigned)(st >> 62);
                if (s2 == 0u) continue;
                pfx += (int)(unsigned)(st & 0xffffffffULL);
                if (s2 == 2u) break;
                --p;
            }
        }
        ts[b] = (2ULL << 62) | (unsigned)(pfx + total);
        s_prefix = pfx;
    }
    __syncthreads();
    if (i < N) {
        int off = s_prefix + incl - v;
        g_off[i] = off;
        g_cur[i] = off;
    }
}

__global__ void k_build(const int* __restrict__ rowp,
                        const int* __restrict__ colp, int E) {
    int base = (blockIdx.x * blockDim.x + threadIdx.x) * 4;
    if (base >= E) return;
    int n = min(4, E - base);

    int r[4], c[4], pos[4];
    float dr[4], dc[4];
    #pragma unroll
    for (int k = 0; k < 4; k++) if (k < n) { r[k] = __ldg(&rowp[base+k]); c[k] = __ldg(&colp[base+k]); }
    #pragma unroll
    for (int k = 0; k < 4; k++) if (k < n) pos[k] = atomicAdd(&g_cur[c[k]], 1);
    #pragma unroll
    for (int k = 0; k < 4; k++) if (k < n) { dr[k] = g_dinv[r[k]]; dc[k] = g_dinv[c[k]]; }
    #pragma unroll
    for (int k = 0; k < 4; k++) if (k < n)
        g_epack[pos[k]] = make_int2(r[k], __float_as_int(dr[k] * dc[k]));
}

// ---------------- Layer 0 (validated body + g_s store + scaled output) ----
__global__ void __launch_bounds__(256) k_layer0(
        const float* __restrict__ hin, float* __restrict__ hout,
        const float* __restrict__ W, const float* __restrict__ b, int N) {
    __shared__ float sW[4 * EMB];
    __shared__ float sB[EMB];
    for (int t = threadIdx.x; t < 4 * EMB; t += blockDim.x) sW[t] = W[t];
    if (threadIdx.x < EMB) sB[threadIdx.x] = b[threadIdx.x];
    __syncthreads();

    int hw     = threadIdx.x >> 4;
    int lane16 = threadIdx.x & 15;
    unsigned hmask = 0xFFFFu << (((threadIdx.x & 31) >> 4) << 4);

    int i = blockIdx.x * 16 + hw;
    if (i >= N) return;

    float di = g_dinv[i];
    float sn = di * di;
    float acc = (lane16 < 4) ? sn * __ldg(&hin[(size_t)i * 4 + lane16]) : 0.f;
    float s   = sn;

    int beg = g_off[i];
    int cnt = g_deg[i];
    const int2* ep = g_epack + beg;

    int j0 = 0;
    for (; j0 + 16 <= cnt; j0 += 16) {
        int2 e = __ldg(&ep[j0 + lane16]);
        #pragma unroll
        for (int q = 0; q < 16; q++) {
            int   r  = __shfl_sync(hmask, e.x, q, 16);
            float nm = __int_as_float(__shfl_sync(hmask, e.y, q, 16));
            s += nm;
            float hv = (lane16 < 4) ? __ldg(&hin[(size_t)r * 4 + lane16]) : 0.f;
            acc = fmaf(nm, hv, acc);
        }
    }
    int rem = cnt - j0;
    if (rem > 0) {
        int2 e = (lane16 < rem) ? __ldg(&ep[j0 + lane16]) : make_int2(0, 0);
        for (int q = 0; q < rem; q++) {
            int   r  = __shfl_sync(hmask, e.x, q, 16);
            float nm = __int_as_float(__shfl_sync(hmask, e.y, q, 16));
            s += nm;
            float hv = (lane16 < 4) ? __ldg(&hin[(size_t)r * 4 + lane16]) : 0.f;
            acc = fmaf(nm, hv, acc);
        }
    }

    if (lane16 == 0) g_s[i] = s;            // layer-invariant; cached for L1-3

    int k = (lane16 < EMB) ? lane16 : 0;
    float o = s * sB[k];
    #pragma unroll
    for (int f = 0; f < 4; f++) {
        float af = __shfl_sync(hmask, acc, f, 16);
        o = fmaf(af, sW[f * EMB + k], o);
    }
    float res = (lane16 < EMB) ? di * tanhf(o) : 0.f;   // PRE-SCALED output
    hout[(size_t)i * 16 + lane16] = res;
}

// ---------------- Layers 1-3: pre-scaled input, reduced inner loop --------
// hin rows are ĥ = dinv*h. acc = ĥ_i + Σ_edges ĥ_r;  o = s*b + (di*acc)@W
template<bool SCALED_OUT>
__global__ void __launch_bounds__(256) k_layer12(
        const float* __restrict__ hin, float* __restrict__ hout,
        const float* __restrict__ W, const float* __restrict__ b, int N) {
    __shared__ float sW[12 * EMB];
    __shared__ float sB[EMB];
    for (int t = threadIdx.x; t < 12 * EMB; t += blockDim.x) sW[t] = W[t];
    if (threadIdx.x < EMB) sB[threadIdx.x] = b[threadIdx.x];
    __syncthreads();

    int hw     = threadIdx.x >> 4;
    int lane16 = threadIdx.x & 15;
    unsigned hmask = 0xFFFFu << (((threadIdx.x & 31) >> 4) << 4);

    int i = blockIdx.x * 16 + hw;
    if (i >= N) return;

    float di  = g_dinv[i];
    float acc = (lane16 < 12) ? __ldg(&hin[(size_t)i * 16 + lane16]) : 0.f;  // self ĥ_i

    int beg = g_off[i];
    int cnt = g_deg[i];
    const int2* ep = g_epack + beg;

    int j0 = 0;
    for (; j0 + 16 <= cnt; j0 += 16) {
        int2 e = __ldg(&ep[j0 + lane16]);
        #pragma unroll
        for (int q = 0; q < 16; q++) {
            int r = __shfl_sync(hmask, e.x, q, 16);
            float hv = (lane16 < 12) ? __ldg(&hin[(size_t)r * 16 + lane16]) : 0.f;
            acc += hv;
        }
    }
    int rem = cnt - j0;
    if (rem > 0) {
        int2 e = (lane16 < rem) ? __ldg(&ep[j0 + lane16]) : make_int2(0, 0);
        for (int q = 0; q < rem; q++) {
            int r = __shfl_sync(hmask, e.x, q, 16);
            float hv = (lane16 < 12) ? __ldg(&hin[(size_t)r * 16 + lane16]) : 0.f;
            acc += hv;
        }
    }

    float s    = __ldg(&g_s[i]);
    float tacc = di * acc;
    int k = (lane16 < EMB) ? lane16 : 0;
    float o = s * sB[k];
    #pragma unroll
    for (int f = 0; f < 12; f++) {
        float af = __shfl_sync(hmask, tacc, f, 16);
        o = fmaf(af, sW[f * EMB + k], o);
    }
    float res = tanhf(o);
    if (SCALED_OUT) res *= di;
    hout[(size_t)i * 16 + lane16] = (lane16 < EMB) ? res : 0.f;
}

// ---------------- pooling (validated) ----------------
__global__ void k_pool(const float* __restrict__ h,
                       const int* __restrict__ batch, int N) {
    int i = blockIdx.x * blockDim.x + threadIdx.x;
    bool act = i < N;
    int g = act ? batch[i] : -1;
    float v[EMB];
    if (act) {
        const float4* hp = (const float4*)(h + (size_t)i * 16);
        float4 a = hp[0], bq = hp[1], c = hp[2];
        v[0]=a.x; v[1]=a.y; v[2]=a.z; v[3]=a.w;
        v[4]=bq.x; v[5]=bq.y; v[6]=bq.z; v[7]=bq.w;
        v[8]=c.x; v[9]=c.y; v[10]=c.z; v[11]=c.w;
    } else {
        #pragma unroll
        for (int f = 0; f < EMB; f++) v[f] = 0.f;
    }
    unsigned full = 0xFFFFFFFFu;
    int g0 = __shfl_sync(full, g, 0);
    bool uni = __all_sync(full, g == g0);
    int lane = threadIdx.x & 31;

    if (uni && g0 >= 0) {
        float sm[EMB], mx[EMB];
        #pragma unroll
        for (int f = 0; f < EMB; f++) { sm[f] = v[f]; mx[f] = v[f]; }
        #pragma unroll
        for (int o = 16; o > 0; o >>= 1) {
            #pragma unroll
            for (int f = 0; f < EMB; f++) {
                sm[f] += __shfl_down_sync(full, sm[f], o);
                mx[f] = fmaxf(mx[f], __shfl_down_sync(full, mx[f], o));
            }
        }
        if (lane == 0) {
            #pragma unroll
            for (int f = 0; f < EMB; f++) {
                atomicAdd(&g_gsum[g0 * EMB + f], sm[f]);
                atomicMaxF(&g_gmax[g0 * EMB + f], mx[f]);
            }
            atomicAdd(&g_cnt[g0], 32.f);
        }
    } else if (act) {
        #pragma unroll
        for (int f = 0; f < EMB; f++) {
            atomicAdd(&g_gsum[g * EMB + f], v[f]);
            atomicMaxF(&g_gmax[g * EMB + f], v[f]);
        }
        atomicAdd(&g_cnt[g], 1.f);
    }
}

// ---------------- head (validated) ----------------
__global__ void k_final(const float* __restrict__ Wout, const float* __restrict__ bout,
                        float* __restrict__ out, int G) {
    int g = blockIdx.x;
    int t = threadIdx.x;
    __shared__ float hid[2 * EMB];
    if (t < 2 * EMB) {
        float v;
        if (t < EMB) v = g_gmax[g * EMB + t];
        else         v = g_gsum[g * EMB + (t - EMB)] / fmaxf(g_cnt[g], 1.f);
        hid[t] = v;
        out[(size_t)G * 17 + (size_t)g * 24 + t] = v;
    }
    __syncthreads();
    if (t < 17) {
        float o = bout[t];
        #pragma unroll
        for (int f = 0; f < 2 * EMB; f++) o += hid[f] * Wout[f * 17 + t];
        out[(size_t)g * 17 + t] = o;
    }
}

// ---------------- launch ----------------
extern "C" void kernel_launch(void* const* d_in, const int* in_sizes, int n_in,
                              void* d_out, int out_size) {
    const float* x     = (const float*)d_in[0];
    int*         ebuf  = (int*)        d_in[1];   // edge_index buffer (repurposed, restored)
    const int*   batch = (const int*)  d_in[2];
    const float* W0 = (const float*)d_in[3],  *b0 = (const float*)d_in[4];
    const float* W1 = (const float*)d_in[5],  *b1 = (const float*)d_in[6];
    const float* W2 = (const float*)d_in[7],  *b2 = (const float*)d_in[8];
    const float* W3 = (const float*)d_in[9],  *b3 = (const float*)d_in[10];
    const float* Wo = (const float*)d_in[11], *bo = (const float*)d_in[12];
    float* out = (float*)d_out;

    const int N = in_sizes[0] / 4;
    const int E = in_sizes[1] / 2;
    const int G = out_size / 41;           // 17 + 24 per graph

    // ---- scratch symbol addresses ----
    void *pDeg, *pGsum, *pGmax, *pCnt, *pTs, *pStash, *pHa, *pHb;
    cudaGetSymbolAddress(&pDeg,   g_deg);
    cudaGetSymbolAddress(&pGsum,  g_gsum);
    cudaGetSymbolAddress(&pGmax,  g_gmax);
    cudaGetSymbolAddress(&pCnt,   g_cnt);
    cudaGetSymbolAddress(&pTs,    g_tilestat);
    cudaGetSymbolAddress(&pStash, g_stash);
    cudaGetSymbolAddress(&pHa,    g_ha);
    cudaGetSymbolAddress(&pHb,    g_hb);

    // ---- init via memset nodes (validated) ----
    cudaMemsetAsync(pDeg,  0,    (size_t)N * sizeof(int), 0);
    cudaMemsetAsync(pGsum, 0,    (size_t)G * EMB * sizeof(float), 0);
    cudaMemsetAsync(pGmax, 0xFF, (size_t)G * EMB * sizeof(float), 0);   // -NaN ≡ -inf for atomicMaxF
    cudaMemsetAsync(pCnt,  0,    (size_t)G * sizeof(float), 0);
    cudaMemsetAsync(pTs,   0,    512 * sizeof(unsigned long long), 0);

    // ---- stash edge_index; its buffer becomes h ping/pong (2MB pages) ----
    cudaMemcpyAsync(pStash, ebuf, (size_t)2 * E * sizeof(int),
                    cudaMemcpyDeviceToDevice, 0);
    const int* srow = (const int*)pStash;
    const int* scol = srow + E;

    float* hA;
    float* hB;
    if ((size_t)2 * E * sizeof(int) >= (size_t)2 * N * 16 * sizeof(float)) {
        hA = (float*)ebuf;
        hB = hA + (size_t)N * 16;
    } else {
        hA = (float*)pHa;
        hB = (float*)pHb;
    }

    const int T = 256;
    int nbN   = (N + T - 1) / T;
    int nbE4  = (E + T * 4 - 1) / (T * 4);
    int nScan = (N + 1023) / 1024;
    int nbL   = (N + 15) / 16;

    k_deg<<<nbE4, T>>>(scol, E);                          // 0 (reads stash)
    k_scan<<<nScan, 1024>>>(N);                           // 1
    k_build<<<nbE4, T>>>(srow, scol, E);                  // 2 (reads stash)

    // x -> hA(scaled) -> hB(scaled) -> hA(scaled) -> hB(plain); pool(hB)
    k_layer0        <<<nbL, T>>>(x,  hA, W0, b0, N);      // 3 <- PROFILED
    k_layer12<true> <<<nbL, T>>>(hA, hB, W1, b1, N);      // 4
    k_layer12<true> <<<nbL, T>>>(hB, hA, W2, b2, N);      // 5
    k_layer12<false><<<nbL, T>>>(hA, hB, W3, b3, N);      // 6

    k_pool<<<nbN, T>>>(hB, batch, N);                     // 7
    k_final<<<G, 32>>>(Wo, bo, out, G);                   // 8

    // ---- restore edge_index buffer (determinism across replays) ----
    cudaMemcpyAsync(ebuf, pStash, (size_t)2 * E * sizeof(int),
                    cudaMemcpyDeviceToDevice, 0);
}